// round 14
// baseline (speedup 1.0000x reference)
#include <cuda_runtime.h>

#define IMG_H 512
#define IMG_W 512

__global__ __launch_bounds__(128, 5)   // cap regs (~102) -> 5 CTAs/SM, 20 warps
void cheby_smooth_kernel(const float* __restrict__ x,
                         const float* __restrict__ f,
                         const float* __restrict__ kA,
                         float* __restrict__ out)
{
    const int b    = blockIdx.z;
    const int lane = threadIdx.x;                                 // blockDim.x == 32
    const int r0   = (blockIdx.y * 4 + threadIdx.y) * 8;          // first of 8 output rows
    const int c0   = (blockIdx.x * 32 + lane) * 4;                // first of 4 output cols

    __shared__ float k[9];
    if (threadIdx.y == 0 && lane < 9)
        k[lane] = kA[b * 9 + lane];
    __syncthreads();

    const size_t base = (size_t)b * IMG_H * IMG_W;
    const float* __restrict__ xb = x + base;
    const float* __restrict__ fb = f + base;
    float* __restrict__ ob = out + base;

    // ---- Phase 1: front-batch ONLY the x loads (critical-path MLP) ----
    float4 mid[10];
    float  lf[10], rt[10];

    #pragma unroll
    for (int i = 0; i < 10; ++i) {
        const int rr = r0 - 1 + i;
        const bool valid = (rr >= 0) && (rr < IMG_H);
        const float* __restrict__ row = xb + (size_t)rr * IMG_W;
        mid[i] = valid ? *reinterpret_cast<const float4*>(row + c0)
                       : make_float4(0.f, 0.f, 0.f, 0.f);
        lf[i] = (lane == 0  && valid && c0 > 0)         ? row[c0 - 1] : 0.f;
        rt[i] = (lane == 31 && valid && c0 + 4 < IMG_W) ? row[c0 + 4] : 0.f;
    }

    // ---- Phase 2: intra-warp halo exchange ----
    #pragma unroll
    for (int i = 0; i < 10; ++i) {
        const float l = __shfl_up_sync(0xffffffffu, mid[i].w, 1);
        const float r = __shfl_down_sync(0xffffffffu, mid[i].x, 1);
        if (lane != 0)  lf[i] = l;
        if (lane != 31) rt[i] = r;
    }

    // ---- Phase 3: compute 8 output rows; f loaded per-row (touch-once, hidden by TLP) ----
    const float inv6 = 1.0f / 6.0f;

    #pragma unroll
    for (int j = 0; j < 8; ++j) {
        // Issue this row's f load first so it overlaps the FMA chain below.
        const float4 fv = *reinterpret_cast<const float4*>(fb + (size_t)(r0 + j) * IMG_W + c0);

        float a0 = 0.f, a1 = 0.f, a2 = 0.f, a3 = 0.f;
        #pragma unroll
        for (int t = 0; t < 3; ++t) {
            const int i = j + t;
            const float k0 = k[t * 3 + 0];
            const float k1 = k[t * 3 + 1];
            const float k2 = k[t * 3 + 2];
            a0 = fmaf(lf[i],    k0, fmaf(mid[i].x, k1, fmaf(mid[i].y, k2, a0)));
            a1 = fmaf(mid[i].x, k0, fmaf(mid[i].y, k1, fmaf(mid[i].z, k2, a1)));
            a2 = fmaf(mid[i].y, k0, fmaf(mid[i].z, k1, fmaf(mid[i].w, k2, a2)));
            a3 = fmaf(mid[i].z, k0, fmaf(mid[i].w, k1, fmaf(rt[i],    k2, a3)));
        }
        const float4 xc = mid[j + 1];
        float4 o;
        o.x = xc.x + (fv.x - a0) * inv6;
        o.y = xc.y + (fv.y - a1) * inv6;
        o.z = xc.z + (fv.z - a2) * inv6;
        o.w = xc.w + (fv.w - a3) * inv6;
        *reinterpret_cast<float4*>(ob + (size_t)(r0 + j) * IMG_W + c0) = o;
    }
}

extern "C" void kernel_launch(void* const* d_in, const int* in_sizes, int n_in,
                              void* d_out, int out_size)
{
    const float* x  = (const float*)d_in[0];   // [64,1,512,512]
    const float* f  = (const float*)d_in[1];   // [64,1,512,512]
    const float* kA = (const float*)d_in[2];   // [64,1,3,3]
    float* out = (float*)d_out;

    dim3 block(32, 4, 1);
    dim3 grid(IMG_W / (32 * 4), IMG_H / (4 * 8), 64); // (4, 16, 64)
    cheby_smooth_kernel<<<grid, block>>>(x, f, kA, out);
}

// round 15
// speedup vs baseline: 1.1200x; 1.1200x over previous
#include <cuda_runtime.h>

#define IMG_H 512
#define IMG_W 512

__global__ __launch_bounds__(128)
void cheby_smooth_kernel(const float* __restrict__ x,
                         const float* __restrict__ f,
                         const float* __restrict__ kA,
                         float* __restrict__ out)
{
    const int b    = blockIdx.z;
    const int lane = threadIdx.x;                                 // blockDim.x == 32
    const int r0   = (blockIdx.y * 4 + threadIdx.y) * 8;          // first of 8 output rows
    const int c0   = (blockIdx.x * 32 + lane) * 4;                // first of 4 output cols

    // Stage this batch's 3x3 kernel into smem (one broadcast load per block).
    __shared__ float k[9];
    if (threadIdx.y == 0 && lane < 9)
        k[lane] = kA[b * 9 + lane];
    __syncthreads();

    const size_t base = (size_t)b * IMG_H * IMG_W;
    const float* __restrict__ xb = x + base;
    const float* __restrict__ fb = f + base;
    float* __restrict__ ob = out + base;

    // ---- Phase 1: issue ALL global loads up front (max MLP), DEFAULT cache policy ----
    float4 mid[10];
    float  lf[10], rt[10];

    #pragma unroll
    for (int i = 0; i < 10; ++i) {
        const int rr = r0 - 1 + i;
        const bool valid = (rr >= 0) && (rr < IMG_H);
        const float* __restrict__ row = xb + (size_t)rr * IMG_W;
        mid[i] = valid ? *reinterpret_cast<const float4*>(row + c0)
                       : make_float4(0.f, 0.f, 0.f, 0.f);
        // Only lanes 0 / 31 need a real boundary element (predicated scalar LDG).
        lf[i] = (lane == 0  && valid && c0 > 0)         ? row[c0 - 1] : 0.f;
        rt[i] = (lane == 31 && valid && c0 + 4 < IMG_W) ? row[c0 + 4] : 0.f;
    }

    float4 fv[8];
    #pragma unroll
    for (int j = 0; j < 8; ++j)
        fv[j] = *reinterpret_cast<const float4*>(fb + (size_t)(r0 + j) * IMG_W + c0);

    // ---- Phase 2: intra-warp halo exchange ----
    #pragma unroll
    for (int i = 0; i < 10; ++i) {
        const float l = __shfl_up_sync(0xffffffffu, mid[i].w, 1);
        const float r = __shfl_down_sync(0xffffffffu, mid[i].x, 1);
        if (lane != 0)  lf[i] = l;
        if (lane != 31) rt[i] = r;
    }

    // ---- Phase 3: compute 8 output rows ----
    const float inv6 = 1.0f / 6.0f;

    #pragma unroll
    for (int j = 0; j < 8; ++j) {
        float a0 = 0.f, a1 = 0.f, a2 = 0.f, a3 = 0.f;
        #pragma unroll
        for (int t = 0; t < 3; ++t) {
            const int i = j + t;
            const float k0 = k[t * 3 + 0];
            const float k1 = k[t * 3 + 1];
            const float k2 = k[t * 3 + 2];
            a0 = fmaf(lf[i],    k0, fmaf(mid[i].x, k1, fmaf(mid[i].y, k2, a0)));
            a1 = fmaf(mid[i].x, k0, fmaf(mid[i].y, k1, fmaf(mid[i].z, k2, a1)));
            a2 = fmaf(mid[i].y, k0, fmaf(mid[i].z, k1, fmaf(mid[i].w, k2, a2)));
            a3 = fmaf(mid[i].z, k0, fmaf(mid[i].w, k1, fmaf(rt[i],    k2, a3)));
        }
        const float4 xc = mid[j + 1];
        float4 o;
        o.x = xc.x + (fv[j].x - a0) * inv6;
        o.y = xc.y + (fv[j].y - a1) * inv6;
        o.z = xc.z + (fv[j].z - a2) * inv6;
        o.w = xc.w + (fv[j].w - a3) * inv6;
        // Streaming store ONLY: out is write-once; keep it from displacing x/f in L2.
        __stcs(reinterpret_cast<float4*>(ob + (size_t)(r0 + j) * IMG_W + c0), o);
    }
}

extern "C" void kernel_launch(void* const* d_in, const int* in_sizes, int n_in,
                              void* d_out, int out_size)
{
    const float* x  = (const float*)d_in[0];   // [64,1,512,512]
    const float* f  = (const float*)d_in[1];   // [64,1,512,512]
    const float* kA = (const float*)d_in[2];   // [64,1,3,3]
    float* out = (float*)d_out;

    dim3 block(32, 4, 1);
    dim3 grid(IMG_W / (32 * 4), IMG_H / (4 * 8), 64); // (4, 16, 64)
    cheby_smooth_kernel<<<grid, block>>>(x, f, kA, out);
}